// round 1
// baseline (speedup 1.0000x reference)
#include <cuda_runtime.h>
#include <cuda_bf16.h>
#include <math.h>

#define HW 9216     // 96*96
#define DIM 96
#define NSAMP 8
#define NBLK 16     // sample * direction
#define TPB 1024
#define INFG 20000  // > 96, INFG^2 fits comfortably in int32

__device__ float g_dists[NBLK];

__global__ __launch_bounds__(TPB, 1)
void hausdorff_edt_kernel(const float* __restrict__ predict,
                          const float* __restrict__ target)
{
    const int blk = blockIdx.x;
    const int s   = blk >> 1;      // sample
    const int dir = blk & 1;       // 0: src=A\B, tgt=B ; 1: src=B\A, tgt=A
    const int tid = threadIdx.x;

    __shared__ unsigned char srcm[HW];   // source mask per pixel
    __shared__ unsigned char tgm[HW];    // target mask per pixel
    __shared__ short gcol[HW];           // per-column 1D distance (rows)
    __shared__ int   warpmax[32];

    // ---- build masks (round-half-to-even like jnp.round) ----
    const float* p = predict + s * HW;
    const float* t = target  + s * HW;
    #pragma unroll
    for (int q = tid; q < HW; q += TPB) {
        bool a = rintf(p[q]) > 0.5f;
        bool b = rintf(t[q]) > 0.5f;
        bool sb, tb;
        if (dir == 0) { sb = a && !b; tb = b; }
        else          { sb = b && !a; tb = a; }
        srcm[q] = (unsigned char)sb;
        tgm[q]  = (unsigned char)tb;
    }
    __syncthreads();

    // ---- phase 1: per-column nearest-set-row distance (two-pass scan) ----
    if (tid < DIM) {
        const int j = tid;
        int d = INFG;
        #pragma unroll
        for (int i = 0; i < DIM; ++i) {
            d = tgm[i * DIM + j] ? 0 : (d + 1);
            gcol[i * DIM + j] = (short)d;
        }
        d = INFG;
        #pragma unroll
        for (int i = DIM - 1; i >= 0; --i) {
            d = tgm[i * DIM + j] ? 0 : (d + 1);
            int cur = gcol[i * DIM + j];
            gcol[i * DIM + j] = (short)(d < cur ? d : cur);
        }
    }
    __syncthreads();

    // ---- phase 2: squared EDT at src pixels, track max ----
    int maxd2 = -1;   // sentinel: no source point seen
    #pragma unroll
    for (int rep = 0; rep < HW / TPB; ++rep) {   // 9216/1024 = 9 pixels/thread
        int q = rep * TPB + tid;
        if (srcm[q]) {
            int i = q / DIM;
            int j = q - i * DIM;
            const short* grow = &gcol[i * DIM];
            int m0 = 0x7fffffff, m1 = 0x7fffffff;
            #pragma unroll
            for (int jp = 0; jp < DIM; jp += 2) {
                int g0 = grow[jp];
                int g1 = grow[jp + 1];
                int dj0 = j - jp;
                int dj1 = j - jp - 1;
                int d0 = g0 * g0 + dj0 * dj0;
                int d1 = g1 * g1 + dj1 * dj1;
                m0 = min(m0, d0);
                m1 = min(m1, d1);
            }
            int m = min(m0, m1);
            maxd2 = max(maxd2, m);
        }
    }

    // ---- block max-reduce ----
    int v = maxd2;
    #pragma unroll
    for (int off = 16; off > 0; off >>= 1)
        v = max(v, __shfl_xor_sync(0xffffffffu, v, off));
    if ((tid & 31) == 0) warpmax[tid >> 5] = v;
    __syncthreads();
    if (tid < 32) {
        int v2 = warpmax[tid];
        #pragma unroll
        for (int off = 16; off > 0; off >>= 1)
            v2 = max(v2, __shfl_xor_sync(0xffffffffu, v2, off));
        if (tid == 0) {
            float dist;
            if (v2 < 0)             dist = 0.0f;        // empty source set
            else if (v2 > 1000000)  dist = 1e9f;        // empty target set (BIG)
            else                    dist = sqrtf((float)v2) * (1.0f / (float)DIM);
            g_dists[blk] = dist;
        }
    }
}

__global__ void hausdorff_reduce_kernel(float* __restrict__ out)
{
    if (threadIdx.x == 0) {
        float acc = 0.0f;
        #pragma unroll
        for (int s = 0; s < NSAMP; ++s)
            acc += fmaxf(g_dists[2 * s], g_dists[2 * s + 1]);
        out[0] = acc * (1.0f / (float)NSAMP);
    }
}

extern "C" void kernel_launch(void* const* d_in, const int* in_sizes, int n_in,
                              void* d_out, int out_size)
{
    const float* predict = (const float*)d_in[0];
    const float* target  = (const float*)d_in[1];
    float* out = (float*)d_out;

    hausdorff_edt_kernel<<<NBLK, TPB>>>(predict, target);
    hausdorff_reduce_kernel<<<1, 32>>>(out);
}

// round 2
// speedup vs baseline: 2.6175x; 2.6175x over previous
#include <cuda_runtime.h>
#include <cuda_bf16.h>
#include <math.h>

#define HW     9216    // 96*96
#define DIM    96
#define NSAMP  8
#define NBLK16 16      // sample * direction
#define NSLICE 9       // 9216 / 1024 pixel slices per (sample,dir)
#define NCTA   (NBLK16 * NSLICE)   // 144 CTAs = single wave on 148 SMs
#define TPB    1024
#define INFG   20000   // > 96; INFG^2 = 4e8 fits int32

__device__ int g_part[NCTA];
__device__ int g_count = 0;

__global__ __launch_bounds__(TPB, 1)
void hausdorff_kernel(const float* __restrict__ predict,
                      const float* __restrict__ target,
                      float* __restrict__ out)
{
    const int bx    = blockIdx.x;
    const int blk16 = bx & 15;        // (sample, dir)
    const int slice = bx >> 4;        // which 1024-pixel slice this CTA owns
    const int s     = blk16 >> 1;
    const int dir   = blk16 & 1;
    const int tid   = threadIdx.x;

    __shared__ unsigned char srcm[HW];
    __shared__ unsigned char tgm[HW];
    __shared__ short gF[HW];          // forward column scan
    __shared__ short gB[HW];          // backward column scan
    __shared__ int   gsq[HW];         // min(gF,gB)^2
    __shared__ int   warpmax[32];
    __shared__ int   lastflag;

    // ---- build masks (round-half-to-even like jnp.round) ----
    const float* p = predict + s * HW;
    const float* t = target  + s * HW;
    #pragma unroll
    for (int r = 0; r < HW / TPB; ++r) {
        int q = r * TPB + tid;
        bool a = rintf(p[q]) > 0.5f;
        bool b = rintf(t[q]) > 0.5f;
        bool sb, tb;
        if (dir == 0) { sb = a && !b; tb = b; }
        else          { sb = b && !a; tb = a; }
        srcm[q] = (unsigned char)sb;
        tgm[q]  = (unsigned char)tb;
    }
    __syncthreads();

    // ---- phase 1: per-column nearest-set-row distance, fwd/bwd in parallel ----
    if (tid < DIM) {
        const int j = tid;
        int d = INFG;
        #pragma unroll
        for (int i = 0; i < DIM; ++i) {
            d = tgm[i * DIM + j] ? 0 : (d + 1);
            gF[i * DIM + j] = (short)d;
        }
    } else if (tid < 2 * DIM) {
        const int j = tid - DIM;
        int d = INFG;
        #pragma unroll
        for (int i = DIM - 1; i >= 0; --i) {
            d = tgm[i * DIM + j] ? 0 : (d + 1);
            gB[i * DIM + j] = (short)d;
        }
    }
    __syncthreads();

    // ---- combine + square into int array (enables int4 loads in hot loop) ----
    #pragma unroll
    for (int r = 0; r < HW / TPB; ++r) {
        int q = r * TPB + tid;
        int f = gF[q];
        int b = gB[q];
        int g = min(f, b);
        gsq[q] = g * g;
    }
    __syncthreads();

    // ---- phase 2: squared EDT at this CTA's single pixel ----
    int maxd2 = -1;   // sentinel: no source point
    {
        const int q = slice * TPB + tid;
        if (srcm[q]) {
            const int i = q / DIM;
            const int j = q - i * DIM;
            const int* grow = &gsq[i * DIM];   // 16B aligned (384B row stride)
            int m0 = 0x7fffffff, m1 = 0x7fffffff, m2 = 0x7fffffff, m3 = 0x7fffffff;
            #pragma unroll
            for (int jp = 0; jp < DIM; jp += 4) {
                int4 gg = *(const int4*)&grow[jp];
                int e0 = j - jp, e1 = j - jp - 1, e2 = j - jp - 2, e3 = j - jp - 3;
                m0 = min(m0, gg.x + e0 * e0);
                m1 = min(m1, gg.y + e1 * e1);
                m2 = min(m2, gg.z + e2 * e2);
                m3 = min(m3, gg.w + e3 * e3);
            }
            maxd2 = min(min(m0, m1), min(m2, m3));
        }
    }

    // ---- block max-reduce ----
    int v = maxd2;
    #pragma unroll
    for (int off = 16; off > 0; off >>= 1)
        v = max(v, __shfl_xor_sync(0xffffffffu, v, off));
    if ((tid & 31) == 0) warpmax[tid >> 5] = v;
    __syncthreads();
    if (tid < 32) {
        int v2 = warpmax[tid];
        #pragma unroll
        for (int off = 16; off > 0; off >>= 1)
            v2 = max(v2, __shfl_xor_sync(0xffffffffu, v2, off));
        if (tid == 0) {
            g_part[bx] = v2;
            __threadfence();
            int prev = atomicAdd(&g_count, 1);
            lastflag = (prev == NCTA - 1);
        }
    }
    __syncthreads();

    // ---- last CTA finalizes: per-(s,dir) max over slices, mean over samples ----
    if (lastflag && tid < 32) {
        float dist = 0.0f;
        if (tid < NBLK16) {
            int vmax = -1;
            #pragma unroll
            for (int k = 0; k < NSLICE; ++k)
                vmax = max(vmax, __ldcg(&g_part[k * NBLK16 + tid]));
            if (vmax < 0)            dist = 0.0f;   // empty source set
            else if (vmax > 1000000) dist = 1e9f;   // empty target set -> BIG
            else                     dist = sqrtf((float)vmax) * (1.0f / (float)DIM);
        }
        float acc = 0.0f;
        #pragma unroll
        for (int ss = 0; ss < NSAMP; ++ss) {
            float d0 = __shfl_sync(0xffffffffu, dist, 2 * ss);
            float d1 = __shfl_sync(0xffffffffu, dist, 2 * ss + 1);
            acc += fmaxf(d0, d1);
        }
        if (tid == 0) {
            out[0] = acc * (1.0f / (float)NSAMP);
            g_count = 0;   // reset for next graph replay
        }
    }
}

extern "C" void kernel_launch(void* const* d_in, const int* in_sizes, int n_in,
                              void* d_out, int out_size)
{
    const float* predict = (const float*)d_in[0];
    const float* target  = (const float*)d_in[1];
    float* out = (float*)d_out;

    hausdorff_kernel<<<NCTA, TPB>>>(predict, target, out);
}